// round 1
// baseline (speedup 1.0000x reference)
#include <cuda_runtime.h>
#include <cuda_bf16.h>
#include <cstdint>

// Fixed problem geometry (reference: H_IMG=352, W_IMG=640, item=0)
#define H_IMG 352
#define W_IMG 640
#define NPIX  (H_IMG * W_IMG)

// Scratch: packed (z_bits << 32 | point_idx) per pixel. Sentinel = all ones.
__device__ unsigned long long g_zidx[NPIX];

static constexpr unsigned long long SENTINEL = 0xFFFFFFFFFFFFFFFFULL;

__global__ void init_kernel() {
    int i = blockIdx.x * blockDim.x + threadIdx.x;
    if (i < NPIX) g_zidx[i] = SENTINEL;
}

__global__ void splat_kernel(const float* __restrict__ means,
                             const float* __restrict__ Kmat,
                             const float* __restrict__ E,
                             int N) {
    int i = blockIdx.x * blockDim.x + threadIdx.x;
    if (i >= N) return;

    float x = means[3 * i + 0];
    float y = means[3 * i + 1];
    float zc = means[3 * i + 2];

    // pts_c = R @ p + t, R = E[:3,:3], t = E[:3,3] (row-major 4x4)
    float px = E[0] * x + E[1] * y + E[2]  * zc + E[3];
    float py = E[4] * x + E[5] * y + E[6]  * zc + E[7];
    float pz = E[8] * x + E[9] * y + E[10] * zc + E[11];

    bool valid = pz > 0.1f;
    float zsafe = valid ? pz : 1.0f;

    float fx = Kmat[0], cx = Kmat[2];
    float fy = Kmat[4], cy = Kmat[5];

    // Match un-contracted f32: (x / z) * f + c, each op IEEE round-to-nearest.
    float ru = __fdiv_rn(px, zsafe);
    float rv = __fdiv_rn(py, zsafe);
    float uf = __fadd_rn(__fmul_rn(ru, fx), cx);
    float vf = __fadd_rn(__fmul_rn(rv, fy), cy);
    int u = (int)uf;   // trunc toward zero, matches astype(int32)
    int v = (int)vf;

    bool inb = valid & (u >= 0) & (u < W_IMG) & (v >= 0) & (v < H_IMG);
    if (!inb) return;

    int pix = v * W_IMG + u;
    unsigned long long packed =
        ((unsigned long long)__float_as_uint(pz) << 32) | (unsigned int)i;
    atomicMin(&g_zidx[pix], packed);
}

__global__ void render_kernel(const float* __restrict__ colours,
                              float* __restrict__ out,
                              int N) {
    int p = blockIdx.x * blockDim.x + threadIdx.x;
    if (p >= NPIX) return;

    unsigned long long v = g_zidx[p];
    float r = 0.f, g = 0.f, b = 0.f;
    if (v != SENTINEL) {
        int idx = (int)(unsigned int)(v & 0xFFFFFFFFULL);
        if (idx < N) {
            const float* c = colours + (size_t)idx * 12;
            float c0 = c[0], c1 = c[1], c2 = c[2];
            r = 1.0f / (1.0f + expf(-c0));
            g = 1.0f / (1.0f + expf(-c1));
            b = 1.0f / (1.0f + expf(-c2));
        }
    }
    out[p]            = r;
    out[NPIX + p]     = g;
    out[2 * NPIX + p] = b;
}

extern "C" void kernel_launch(void* const* d_in, const int* in_sizes, int n_in,
                              void* d_out, int out_size) {
    const float* means   = (const float*)d_in[0];  // [N,3]
    const float* colours = (const float*)d_in[1];  // [N,12]
    const float* Kmat    = (const float*)d_in[2];  // [3,3]
    const float* E       = (const float*)d_in[3];  // [4,4]
    float* out = (float*)d_out;                    // [3,H,W]

    int N = in_sizes[0] / 3;

    const int TPB = 256;
    init_kernel<<<(NPIX + TPB - 1) / TPB, TPB>>>();
    splat_kernel<<<(N + TPB - 1) / TPB, TPB>>>(means, Kmat, E, N);
    render_kernel<<<(NPIX + TPB - 1) / TPB, TPB>>>(colours, out, N);
}